// round 4
// baseline (speedup 1.0000x reference)
#include <cuda_runtime.h>
#include <math.h>
#include <stdint.h>

#define TT 2048
#define HIDDEN 5120
#define NH 32
#define DQ 128
#define DR 64
#define DV 128
#define QLORA 1536
#define KVLORA 512
#define DQK 192   // DQ + DR
#define DKV 256   // DQ + DV

// ---------------- scratch (static device globals; no allocation allowed) ----
__device__ float g_qc[TT * QLORA];
__device__ float g_q[TT * NH * DQK];
__device__ float g_kv[TT * (KVLORA + DR)];
__device__ float g_kvc[TT * KVLORA];
__device__ float g_kvup[TT * NH * DKV];
__device__ float g_qfull[(size_t)NH * TT * DQK];
__device__ float g_kfull[(size_t)NH * TT * DQK];
__device__ float g_vbuf[(size_t)NH * TT * DV];
__device__ float g_attn[TT * NH * DV];

// ---------------- generic SGEMM: C[MxN] = A[MxK] @ B[KxN], row-major fp32 ----
// BM=128, BN=128, BK=8, 256 threads, 8x8 per thread. M%128==0, K%8==0 assumed.
// N may be any multiple of 8 (predicated B loads / C stores).
__global__ __launch_bounds__(256) void sgemm_kernel(
    const float* __restrict__ A, const float* __restrict__ B,
    float* __restrict__ C, int M, int N, int K) {
    __shared__ float As[8][128];
    __shared__ float Bs[8][128];
    const int tid = threadIdx.x;
    const int tr = tid >> 4;          // 0..15
    const int tc = tid & 15;          // 0..15
    const int arow = tid >> 1;        // 0..127
    const int acol = (tid & 1) * 4;   // 0 or 4
    const int brow = tid >> 5;        // 0..7
    const int bcol = (tid & 31) * 4;  // 0..124

    const float* Ab = A + (size_t)(blockIdx.y * 128) * K;
    const int cbase = blockIdx.x * 128;

    float acc[8][8];
#pragma unroll
    for (int i = 0; i < 8; i++)
#pragma unroll
        for (int j = 0; j < 8; j++) acc[i][j] = 0.f;

    for (int k0 = 0; k0 < K; k0 += 8) {
        float4 av = *(const float4*)(Ab + (size_t)arow * K + k0 + acol);
        As[acol + 0][arow] = av.x;
        As[acol + 1][arow] = av.y;
        As[acol + 2][arow] = av.z;
        As[acol + 3][arow] = av.w;
        int bc = cbase + bcol;
        float4 bv = make_float4(0.f, 0.f, 0.f, 0.f);
        if (bc < N) bv = *(const float4*)(B + (size_t)(k0 + brow) * N + bc);
        *(float4*)&Bs[brow][bcol] = bv;
        __syncthreads();
#pragma unroll
        for (int kk = 0; kk < 8; kk++) {
            float ra[8], rb[8];
#pragma unroll
            for (int i = 0; i < 8; i++) ra[i] = As[kk][tr * 8 + i];
#pragma unroll
            for (int j = 0; j < 8; j++) rb[j] = Bs[kk][tc * 8 + j];
#pragma unroll
            for (int i = 0; i < 8; i++)
#pragma unroll
                for (int j = 0; j < 8; j++) acc[i][j] += ra[i] * rb[j];
        }
        __syncthreads();
    }

    const int col = cbase + tc * 8;
    if (col < N) {  // N%8==0, col%8==0 -> full 8 cols valid
#pragma unroll
        for (int i = 0; i < 8; i++) {
            float* Crow = C + (size_t)(blockIdx.y * 128 + tr * 8 + i) * N;
            float4 o0 = make_float4(acc[i][0], acc[i][1], acc[i][2], acc[i][3]);
            float4 o1 = make_float4(acc[i][4], acc[i][5], acc[i][6], acc[i][7]);
            *(float4*)&Crow[col] = o0;
            *(float4*)&Crow[col + 4] = o1;
        }
    }
}

// ---------------- RMSNorm: one block per row ------------------------------
__global__ void rmsnorm_kernel(const float* __restrict__ in,
                               const float* __restrict__ gamma,
                               float* __restrict__ out, int D, int in_stride,
                               int out_stride) {
    const int row = blockIdx.x;
    const float* x = in + (size_t)row * in_stride;
    float* y = out + (size_t)row * out_stride;
    float s = 0.f;
    for (int d = threadIdx.x; d < D; d += blockDim.x) {
        float v = x[d];
        s += v * v;
    }
    __shared__ float red[32];
#pragma unroll
    for (int o = 16; o; o >>= 1) s += __shfl_xor_sync(0xffffffffu, s, o);
    if ((threadIdx.x & 31) == 0) red[threadIdx.x >> 5] = s;
    __syncthreads();
    if (threadIdx.x < 32) {
        float v = (threadIdx.x < (blockDim.x >> 5)) ? red[threadIdx.x] : 0.f;
#pragma unroll
        for (int o = 16; o; o >>= 1) v += __shfl_xor_sync(0xffffffffu, v, o);
        if (threadIdx.x == 0) red[0] = v;
    }
    __syncthreads();
    const float r = rsqrtf(red[0] / (float)D + 1e-6f);
    for (int d = threadIdx.x; d < D; d += blockDim.x) y[d] = x[d] * r * gamma[d];
}

// ---------------- pack + RoPE ---------------------------------------------
// builds qfull[h][t][192] (pre-scaled by 1/sqrt(192)), kfull[h][t][192],
// v[h][t][128]
__global__ void pack_rope_kernel(const int* __restrict__ pos,
                                 const float* __restrict__ q,
                                 const float* __restrict__ kv,
                                 const float* __restrict__ kvup,
                                 float* __restrict__ qfull,
                                 float* __restrict__ kfull,
                                 float* __restrict__ vbuf) {
    const int t = blockIdx.x;
    const int h = blockIdx.y;
    const int d = threadIdx.x;  // 0..191
    const float scale = rsqrtf((float)DQK);
    float qf, kf;
    if (d < DQ) {
        qf = q[(size_t)t * (NH * DQK) + h * DQK + d];
        kf = kvup[(size_t)t * (NH * DKV) + h * DKV + d];
        vbuf[((size_t)h * TT + t) * DV + d] =
            kvup[(size_t)t * (NH * DKV) + h * DKV + DQ + d];
    } else {
        const int d2 = d - DQ;  // 0..63
        const float p = (float)pos[t];
        const float ang = p * powf(10000.f, -((float)(d2 & 31)) / 32.f);
        float c, s;
        sincosf(ang, &s, &c);
        const size_t qb = (size_t)t * (NH * DQK) + h * DQK + DQ;
        float xq = q[qb + d2];
        float xq_o = (d2 & 1) ? q[qb + d2 - 1] : -q[qb + d2 + 1];
        qf = xq * c + xq_o * s;
        const size_t kb = (size_t)t * (KVLORA + DR) + KVLORA;
        float xk = kv[kb + d2];
        float xk_o = (d2 & 1) ? kv[kb + d2 - 1] : -kv[kb + d2 + 1];
        kf = xk * c + xk_o * s;
    }
    qfull[((size_t)h * TT + t) * DQK + d] = qf * scale;
    kfull[((size_t)h * TT + t) * DQK + d] = kf;
}

// ---------------- flash attention (causal) --------------------------------
#define BQ 64
#define BKK 32
#define QSTR 196  // padded row stride for 192-wide rows
#define VSTR 132
#define SSTR 33
#define ATTN_SMEM_FLOATS (BQ * QSTR + BKK * QSTR + BKK * VSTR + BQ * SSTR + 3 * BQ)
#define ATTN_SMEM_BYTES (ATTN_SMEM_FLOATS * 4)

__global__ __launch_bounds__(256) void attn_kernel(
    const float* __restrict__ qfull, const float* __restrict__ kfull,
    const float* __restrict__ vbuf, float* __restrict__ out) {
    extern __shared__ float sm[];
    float* Qs = sm;                    // 64*196
    float* Ks = Qs + BQ * QSTR;        // 32*196
    float* Vs = Ks + BKK * QSTR;       // 32*132
    float* Ss = Vs + BKK * VSTR;       // 64*33
    float* m_sh = Ss + BQ * SSTR;      // 64
    float* l_sh = m_sh + BQ;           // 64
    float* c_sh = l_sh + BQ;           // 64

    const int tid = threadIdx.x;
    const int q0 = blockIdx.x * BQ;
    const int h = blockIdx.y;
    const float* qh = qfull + (size_t)h * TT * DQK;
    const float* kh = kfull + (size_t)h * TT * DQK;
    const float* vh = vbuf + (size_t)h * TT * DV;

    for (int i = tid; i < BQ * (DQK / 4); i += 256) {
        int r = i / 48, c4 = i % 48;
        float4 val = *(const float4*)(qh + (size_t)(q0 + r) * DQK + c4 * 4);
        *(float4*)&Qs[r * QSTR + c4 * 4] = val;
    }
    if (tid < BQ) {
        m_sh[tid] = -1e30f;
        l_sh[tid] = 0.f;
    }

    float acc[32];
#pragma unroll
    for (int i = 0; i < 32; i++) acc[i] = 0.f;

    const int qrow = tid & 63;
    const int dbase = (tid >> 6) * 32;
    const int tq = (tid & 15) * 4;
    const int tk = (tid >> 4) * 2;

    const int nkb = (q0 + BQ) / BKK;  // causal: only blocks touching the triangle
    for (int kb = 0; kb < nkb; kb++) {
        const int k0 = kb * BKK;
        __syncthreads();  // previous iteration's readers done
        for (int i = tid; i < BKK * 48; i += 256) {
            int r = i / 48, c4 = i % 48;
            *(float4*)&Ks[r * QSTR + c4 * 4] =
                *(const float4*)(kh + (size_t)(k0 + r) * DQK + c4 * 4);
        }
        for (int i = tid; i < BKK * 32; i += 256) {
            int r = i / 32, c4 = i % 32;
            *(float4*)&Vs[r * VSTR + c4 * 4] =
                *(const float4*)(vh + (size_t)(k0 + r) * DV + c4 * 4);
        }
        __syncthreads();

        float s[4][2];
#pragma unroll
        for (int i = 0; i < 4; i++) {
            s[i][0] = 0.f;
            s[i][1] = 0.f;
        }
        for (int kk = 0; kk < DQK; kk += 4) {
            float4 k0v = *(float4*)&Ks[tk * QSTR + kk];
            float4 k1v = *(float4*)&Ks[(tk + 1) * QSTR + kk];
#pragma unroll
            for (int i = 0; i < 4; i++) {
                float4 qv = *(float4*)&Qs[(tq + i) * QSTR + kk];
                s[i][0] += qv.x * k0v.x + qv.y * k0v.y + qv.z * k0v.z + qv.w * k0v.w;
                s[i][1] += qv.x * k1v.x + qv.y * k1v.y + qv.z * k1v.z + qv.w * k1v.w;
            }
        }
#pragma unroll
        for (int i = 0; i < 4; i++)
#pragma unroll
            for (int j = 0; j < 2; j++) {
                int kg = k0 + tk + j, qg = q0 + tq + i;
                Ss[(tq + i) * SSTR + tk + j] = (kg <= qg) ? s[i][j] : -1e30f;
            }
        __syncthreads();

        if (tid < BQ) {
            const int r = tid;
            float mo = m_sh[r];
            float mx = mo;
#pragma unroll
            for (int k = 0; k < BKK; k++) mx = fmaxf(mx, Ss[r * SSTR + k]);
            float corr = __expf(mo - mx);
            float sum = 0.f;
#pragma unroll
            for (int k = 0; k < BKK; k++) {
                float p = __expf(Ss[r * SSTR + k] - mx);
                Ss[r * SSTR + k] = p;
                sum += p;
            }
            l_sh[r] = l_sh[r] * corr + sum;
            m_sh[r] = mx;
            c_sh[r] = corr;
        }
        __syncthreads();

        const float corr = c_sh[qrow];
#pragma unroll
        for (int i = 0; i < 32; i++) acc[i] *= corr;
        for (int k = 0; k < BKK; k++) {
            const float p = Ss[qrow * SSTR + k];
            const float* vr = &Vs[k * VSTR + dbase];
#pragma unroll
            for (int i = 0; i < 32; i += 4) {
                float4 vv = *(const float4*)&vr[i];
                acc[i] += p * vv.x;
                acc[i + 1] += p * vv.y;
                acc[i + 2] += p * vv.z;
                acc[i + 3] += p * vv.w;
            }
        }
    }
    __syncthreads();
    const float inv_l = 1.f / l_sh[qrow];
    float* orow = out + (size_t)(q0 + qrow) * (NH * DV) + h * DV + dbase;
#pragma unroll
    for (int i = 0; i < 32; i += 4) {
        float4 o = make_float4(acc[i] * inv_l, acc[i + 1] * inv_l,
                               acc[i + 2] * inv_l, acc[i + 3] * inv_l);
        *(float4*)&orow[i] = o;
    }
}

// ---------------- launch ---------------------------------------------------
extern "C" void kernel_launch(void* const* d_in, const int* in_sizes, int n_in,
                              void* d_out, int out_size) {
    const int* positions = (const int*)d_in[0];
    const float* hidden = (const float*)d_in[1];
    const float* w_qa = (const float*)d_in[2];
    const float* gamma_q = (const float*)d_in[3];
    const float* w_qb = (const float*)d_in[4];
    const float* w_kva = (const float*)d_in[5];
    const float* gamma_kv = (const float*)d_in[6];
    const float* w_kvb = (const float*)d_in[7];
    const float* w_o = (const float*)d_in[8];
    float* out = (float*)d_out;

    float *qc, *q, *kv, *kvc, *kvup, *qf, *kf, *v, *attn;
    cudaGetSymbolAddress((void**)&qc, g_qc);
    cudaGetSymbolAddress((void**)&q, g_q);
    cudaGetSymbolAddress((void**)&kv, g_kv);
    cudaGetSymbolAddress((void**)&kvc, g_kvc);
    cudaGetSymbolAddress((void**)&kvup, g_kvup);
    cudaGetSymbolAddress((void**)&qf, g_qfull);
    cudaGetSymbolAddress((void**)&kf, g_kfull);
    cudaGetSymbolAddress((void**)&v, g_vbuf);
    cudaGetSymbolAddress((void**)&attn, g_attn);

    // 1. q_c_raw = hidden @ w_qa           (2048x5120x1536)
    sgemm_kernel<<<dim3(QLORA / 128, TT / 128), 256>>>(hidden, w_qa, qc, TT,
                                                       QLORA, HIDDEN);
    // 2. rmsnorm(q_c) in place
    rmsnorm_kernel<<<TT, 256>>>(qc, gamma_q, qc, QLORA, QLORA, QLORA);
    // 3. q = q_c @ w_qb                    (2048x1536x6144)
    sgemm_kernel<<<dim3(NH * DQK / 128, TT / 128), 256>>>(qc, w_qb, q, TT,
                                                          NH * DQK, QLORA);
    // 4. kv = hidden @ w_kva               (2048x5120x576)
    sgemm_kernel<<<dim3((KVLORA + DR + 127) / 128, TT / 128), 256>>>(
        hidden, w_kva, kv, TT, KVLORA + DR, HIDDEN);
    // 5. kv_c = rmsnorm(kv[:, :512])
    rmsnorm_kernel<<<TT, 256>>>(kv, gamma_kv, kvc, KVLORA, KVLORA + DR, KVLORA);
    // 6. kv_up = kv_c @ w_kvb              (2048x512x8192)
    sgemm_kernel<<<dim3(NH * DKV / 128, TT / 128), 256>>>(kvc, w_kvb, kvup, TT,
                                                          NH * DKV, KVLORA);
    // 7. pack + RoPE
    pack_rope_kernel<<<dim3(TT, NH), DQK>>>(positions, q, kv, kvup, qf, kf, v);
    // 8. attention
    cudaFuncSetAttribute(attn_kernel, cudaFuncAttributeMaxDynamicSharedMemorySize,
                         ATTN_SMEM_BYTES);
    attn_kernel<<<dim3(TT / BQ, NH), 256, ATTN_SMEM_BYTES>>>(qf, kf, v, attn);
    // 9. out = attn @ w_o                  (2048x4096x5120)
    sgemm_kernel<<<dim3(HIDDEN / 128, TT / 128), 256>>>(attn, w_o, out, TT,
                                                        HIDDEN, NH * DV);
}

// round 5
// speedup vs baseline: 1.5628x; 1.5628x over previous
#include <cuda_runtime.h>
#include <cuda_bf16.h>
#include <math.h>
#include <stdint.h>

#define TT 2048
#define HIDDEN 5120
#define NH 32
#define DQ 128
#define DR 64
#define DV 128
#define QLORA 1536
#define KVLORA 512
#define DQK 192   // DQ + DR
#define DKV 256   // DQ + DV
#define NKVP 640  // kv GEMM N padded to 128 multiple

// ---------------- fp32 scratch ---------------------------------------------
__device__ float g_qc[TT * QLORA];
__device__ float g_q[TT * NH * DQK];
__device__ float g_kv[TT * NKVP];
__device__ float g_kvc[TT * KVLORA];
__device__ float g_kvup[TT * NH * DKV];
__device__ float g_qfull[(size_t)NH * TT * DQK];
__device__ float g_kfull[(size_t)NH * TT * DQK];
__device__ float g_vbuf[(size_t)NH * TT * DV];
__device__ float g_attn[TT * NH * DV];

// ---------------- bf16 split scratch ----------------------------------------
__device__ __nv_bfloat16 g_hid_h[(size_t)TT * HIDDEN], g_hid_l[(size_t)TT * HIDDEN];
__device__ __nv_bfloat16 g_wqa_h[(size_t)HIDDEN * QLORA], g_wqa_l[(size_t)HIDDEN * QLORA];
__device__ __nv_bfloat16 g_wqb_h[(size_t)QLORA * NH * DQK], g_wqb_l[(size_t)QLORA * NH * DQK];
__device__ __nv_bfloat16 g_wkva_h[(size_t)HIDDEN * NKVP], g_wkva_l[(size_t)HIDDEN * NKVP];
__device__ __nv_bfloat16 g_wkvb_h[(size_t)KVLORA * NH * DKV], g_wkvb_l[(size_t)KVLORA * NH * DKV];
__device__ __nv_bfloat16 g_wo_h[(size_t)NH * DV * HIDDEN], g_wo_l[(size_t)NH * DV * HIDDEN];
__device__ __nv_bfloat16 g_qc_h[(size_t)TT * QLORA], g_qc_l[(size_t)TT * QLORA];
__device__ __nv_bfloat16 g_kvc_h[(size_t)TT * KVLORA], g_kvc_l[(size_t)TT * KVLORA];
__device__ __nv_bfloat16 g_at_h[(size_t)TT * NH * DV], g_at_l[(size_t)TT * NH * DV];

// ---------------- split fp32 -> (hi, lo) bf16, optional zero-padded cols ----
__global__ void split_kernel(const float* __restrict__ in,
                             __nv_bfloat16* __restrict__ hi,
                             __nv_bfloat16* __restrict__ lo, int cols,
                             int ostride) {
    const int r = blockIdx.y;
    for (int c = blockIdx.x * blockDim.x + threadIdx.x; c < ostride;
         c += gridDim.x * blockDim.x) {
        float v = (c < cols) ? in[(size_t)r * cols + c] : 0.f;
        __nv_bfloat16 h = __float2bfloat16(v);
        size_t o = (size_t)r * ostride + c;
        hi[o] = h;
        lo[o] = __float2bfloat16(v - __bfloat162float(h));
    }
}

// ---------------- tensor-core GEMM (split bf16, 3 MMAs -> ~fp32 accuracy) ---
// C[MxN] fp32 = (Ah+Al)[MxK] @ (Bh+Bl)[KxN], all bf16 row-major.
// Block 128x128x32, 256 threads, warp tile 32x64, 2-stage cp.async pipeline.
#define GBM 128
#define GBN 128
#define GBK 32
#define ASTR 40    // A smem row stride (bf16): 5 x 16B chunks, coprime with 8
#define BSTR 136   // B smem row stride (bf16): 17 x 16B chunks, coprime with 8
#define A_STAGE (GBM * ASTR)  // 5120 elems
#define B_STAGE (GBK * BSTR)  // 4352 elems
#define GEMM_SMEM_BYTES ((2 * 2 * A_STAGE + 2 * 2 * B_STAGE) * 2)  // 75776

__device__ __forceinline__ void cp16(uint32_t dst, const void* src) {
    asm volatile("cp.async.cg.shared.global [%0], [%1], 16;\n" ::"r"(dst),
                 "l"(src));
}
__device__ __forceinline__ void ldsm4(uint32_t* r, uint32_t addr) {
    asm volatile("ldmatrix.sync.aligned.m8n8.x4.shared.b16 {%0,%1,%2,%3}, [%4];"
                 : "=r"(r[0]), "=r"(r[1]), "=r"(r[2]), "=r"(r[3])
                 : "r"(addr));
}
__device__ __forceinline__ void ldsm4t(uint32_t* r, uint32_t addr) {
    asm volatile(
        "ldmatrix.sync.aligned.m8n8.x4.trans.shared.b16 {%0,%1,%2,%3}, [%4];"
        : "=r"(r[0]), "=r"(r[1]), "=r"(r[2]), "=r"(r[3])
        : "r"(addr));
}
__device__ __forceinline__ void mma16816(float* d, const uint32_t* a,
                                         const uint32_t b0, const uint32_t b1) {
    asm volatile(
        "mma.sync.aligned.m16n8k16.row.col.f32.bf16.bf16.f32 "
        "{%0,%1,%2,%3},{%4,%5,%6,%7},{%8,%9},{%0,%1,%2,%3};"
        : "+f"(d[0]), "+f"(d[1]), "+f"(d[2]), "+f"(d[3])
        : "r"(a[0]), "r"(a[1]), "r"(a[2]), "r"(a[3]), "r"(b0), "r"(b1));
}

__global__ __launch_bounds__(256, 1) void gemm_bf16x3(
    const __nv_bfloat16* __restrict__ Ah, const __nv_bfloat16* __restrict__ Al,
    const __nv_bfloat16* __restrict__ Bh, const __nv_bfloat16* __restrict__ Bl,
    float* __restrict__ C, int M, int N, int K) {
    extern __shared__ __nv_bfloat16 sm[];
    const int tid = threadIdx.x;
    const int lane = tid & 31, wid = tid >> 5;
    const int wm = (wid >> 1) * 32, wn = (wid & 1) * 64;
    const int bm0 = blockIdx.y * GBM, bn0 = blockIdx.x * GBN;

    const uint32_t base = (uint32_t)__cvta_generic_to_shared(sm);
    const uint32_t sAh_b = base;
    const uint32_t sAl_b = base + 2 * A_STAGE * 2;
    const uint32_t sBh_b = base + 4 * A_STAGE * 2;
    const uint32_t sBl_b = sBh_b + 2 * B_STAGE * 2;

    auto prefetch = [&](int k0, int st) {
#pragma unroll
        for (int i = 0; i < 2; i++) {
            int c = tid + i * 256;             // 0..511
            int r = c >> 2, ch = (c & 3) * 8;  // 128 rows x 4 chunks
            size_t goff = (size_t)(bm0 + r) * K + k0 + ch;
            uint32_t soff = (uint32_t)(st * A_STAGE + r * ASTR + ch) * 2;
            cp16(sAh_b + soff, Ah + goff);
            cp16(sAl_b + soff, Al + goff);
        }
#pragma unroll
        for (int i = 0; i < 2; i++) {
            int c = tid + i * 256;
            int r = c >> 4, ch = (c & 15) * 8;  // 32 rows x 16 chunks
            size_t goff = (size_t)(k0 + r) * N + bn0 + ch;
            uint32_t soff = (uint32_t)(st * B_STAGE + r * BSTR + ch) * 2;
            cp16(sBh_b + soff, Bh + goff);
            cp16(sBl_b + soff, Bl + goff);
        }
    };

    float acc[2][8][4];
#pragma unroll
    for (int mi = 0; mi < 2; mi++)
#pragma unroll
        for (int ni = 0; ni < 8; ni++)
#pragma unroll
            for (int j = 0; j < 4; j++) acc[mi][ni][j] = 0.f;

    const int KT = K / GBK;
    prefetch(0, 0);
    asm volatile("cp.async.commit_group;\n");

    for (int kt = 0; kt < KT; kt++) {
        const int st = kt & 1;
        if (kt + 1 < KT) prefetch((kt + 1) * GBK, st ^ 1);
        asm volatile("cp.async.commit_group;\n");
        asm volatile("cp.async.wait_group 1;\n");
        __syncthreads();

#pragma unroll
        for (int kk = 0; kk < GBK; kk += 16) {
            uint32_t ah[2][4], al[2][4];
#pragma unroll
            for (int mi = 0; mi < 2; mi++) {
                int r = wm + mi * 16 + (lane & 15);
                int cc = kk + ((lane >> 4) << 3);
                uint32_t off = (uint32_t)(st * A_STAGE + r * ASTR + cc) * 2;
                ldsm4(ah[mi], sAh_b + off);
                ldsm4(al[mi], sAl_b + off);
            }
            uint32_t bh[4][4], bl[4][4];
#pragma unroll
            for (int n2 = 0; n2 < 4; n2++) {
                int kr = kk + (lane & 15);
                int nc = wn + n2 * 16 + ((lane >> 4) << 3);
                uint32_t off = (uint32_t)(st * B_STAGE + kr * BSTR + nc) * 2;
                ldsm4t(bh[n2], sBh_b + off);
                ldsm4t(bl[n2], sBl_b + off);
            }
#pragma unroll
            for (int mi = 0; mi < 2; mi++)
#pragma unroll
                for (int ni = 0; ni < 8; ni++) {
                    const int n2 = ni >> 1, sl = (ni & 1) * 2;
                    mma16816(acc[mi][ni], ah[mi], bh[n2][sl], bh[n2][sl + 1]);
                    mma16816(acc[mi][ni], ah[mi], bl[n2][sl], bl[n2][sl + 1]);
                    mma16816(acc[mi][ni], al[mi], bh[n2][sl], bh[n2][sl + 1]);
                }
        }
        __syncthreads();
    }

#pragma unroll
    for (int mi = 0; mi < 2; mi++)
#pragma unroll
        for (int ni = 0; ni < 8; ni++) {
            int row = bm0 + wm + mi * 16 + (lane >> 2);
            int col = bn0 + wn + ni * 8 + (lane & 3) * 2;
            *(float2*)&C[(size_t)row * N + col] =
                make_float2(acc[mi][ni][0], acc[mi][ni][1]);
            *(float2*)&C[(size_t)(row + 8) * N + col] =
                make_float2(acc[mi][ni][2], acc[mi][ni][3]);
        }
}

// ---------------- RMSNorm: one block per row ------------------------------
__global__ void rmsnorm_kernel(const float* __restrict__ in,
                               const float* __restrict__ gamma,
                               float* __restrict__ out, int D, int in_stride,
                               int out_stride) {
    const int row = blockIdx.x;
    const float* x = in + (size_t)row * in_stride;
    float* y = out + (size_t)row * out_stride;
    float s = 0.f;
    for (int d = threadIdx.x; d < D; d += blockDim.x) {
        float v = x[d];
        s += v * v;
    }
    __shared__ float red[32];
#pragma unroll
    for (int o = 16; o; o >>= 1) s += __shfl_xor_sync(0xffffffffu, s, o);
    if ((threadIdx.x & 31) == 0) red[threadIdx.x >> 5] = s;
    __syncthreads();
    if (threadIdx.x < 32) {
        float v = (threadIdx.x < (blockDim.x >> 5)) ? red[threadIdx.x] : 0.f;
#pragma unroll
        for (int o = 16; o; o >>= 1) v += __shfl_xor_sync(0xffffffffu, v, o);
        if (threadIdx.x == 0) red[0] = v;
    }
    __syncthreads();
    const float r = rsqrtf(red[0] / (float)D + 1e-6f);
    for (int d = threadIdx.x; d < D; d += blockDim.x) y[d] = x[d] * r * gamma[d];
}

// ---------------- pack + RoPE ---------------------------------------------
__global__ void pack_rope_kernel(const int* __restrict__ pos,
                                 const float* __restrict__ q,
                                 const float* __restrict__ kv,
                                 const float* __restrict__ kvup,
                                 float* __restrict__ qfull,
                                 float* __restrict__ kfull,
                                 float* __restrict__ vbuf) {
    const int t = blockIdx.x;
    const int h = blockIdx.y;
    const int d = threadIdx.x;  // 0..191
    const float scale = rsqrtf((float)DQK);
    float qf, kf;
    if (d < DQ) {
        qf = q[(size_t)t * (NH * DQK) + h * DQK + d];
        kf = kvup[(size_t)t * (NH * DKV) + h * DKV + d];
        vbuf[((size_t)h * TT + t) * DV + d] =
            kvup[(size_t)t * (NH * DKV) + h * DKV + DQ + d];
    } else {
        const int d2 = d - DQ;  // 0..63
        const float p = (float)pos[t];
        const float ang = p * powf(10000.f, -((float)(d2 & 31)) / 32.f);
        float c, s;
        sincosf(ang, &s, &c);
        const size_t qb = (size_t)t * (NH * DQK) + h * DQK + DQ;
        float xq = q[qb + d2];
        float xq_o = (d2 & 1) ? q[qb + d2 - 1] : -q[qb + d2 + 1];
        qf = xq * c + xq_o * s;
        const size_t kb = (size_t)t * NKVP + KVLORA;
        float xk = kv[kb + d2];
        float xk_o = (d2 & 1) ? kv[kb + d2 - 1] : -kv[kb + d2 + 1];
        kf = xk * c + xk_o * s;
    }
    qfull[((size_t)h * TT + t) * DQK + d] = qf * scale;
    kfull[((size_t)h * TT + t) * DQK + d] = kf;
}

// ---------------- flash attention (causal, fp32 SIMT) ----------------------
#define BQ 64
#define BKK 32
#define QSTR 196
#define VSTR 132
#define SSTR 33
#define ATTN_SMEM_FLOATS (BQ * QSTR + BKK * QSTR + BKK * VSTR + BQ * SSTR + 3 * BQ)
#define ATTN_SMEM_BYTES (ATTN_SMEM_FLOATS * 4)

__global__ __launch_bounds__(256) void attn_kernel(
    const float* __restrict__ qfull, const float* __restrict__ kfull,
    const float* __restrict__ vbuf, float* __restrict__ out) {
    extern __shared__ float smf[];
    float* Qs = smf;
    float* Ks = Qs + BQ * QSTR;
    float* Vs = Ks + BKK * QSTR;
    float* Ss = Vs + BKK * VSTR;
    float* m_sh = Ss + BQ * SSTR;
    float* l_sh = m_sh + BQ;
    float* c_sh = l_sh + BQ;

    const int tid = threadIdx.x;
    const int q0 = blockIdx.x * BQ;
    const int h = blockIdx.y;
    const float* qh = qfull + (size_t)h * TT * DQK;
    const float* kh = kfull + (size_t)h * TT * DQK;
    const float* vh = vbuf + (size_t)h * TT * DV;

    for (int i = tid; i < BQ * (DQK / 4); i += 256) {
        int r = i / 48, c4 = i % 48;
        float4 val = *(const float4*)(qh + (size_t)(q0 + r) * DQK + c4 * 4);
        *(float4*)&Qs[r * QSTR + c4 * 4] = val;
    }
    if (tid < BQ) {
        m_sh[tid] = -1e30f;
        l_sh[tid] = 0.f;
    }

    float acc[32];
#pragma unroll
    for (int i = 0; i < 32; i++) acc[i] = 0.f;

    const int qrow = tid & 63;
    const int dbase = (tid >> 6) * 32;
    const int tq = (tid & 15) * 4;
    const int tk = (tid >> 4) * 2;

    const int nkb = (q0 + BQ) / BKK;
    for (int kb = 0; kb < nkb; kb++) {
        const int k0 = kb * BKK;
        __syncthreads();
        for (int i = tid; i < BKK * 48; i += 256) {
            int r = i / 48, c4 = i % 48;
            *(float4*)&Ks[r * QSTR + c4 * 4] =
                *(const float4*)(kh + (size_t)(k0 + r) * DQK + c4 * 4);
        }
        for (int i = tid; i < BKK * 32; i += 256) {
            int r = i / 32, c4 = i % 32;
            *(float4*)&Vs[r * VSTR + c4 * 4] =
                *(const float4*)(vh + (size_t)(k0 + r) * DV + c4 * 4);
        }
        __syncthreads();

        float s[4][2];
#pragma unroll
        for (int i = 0; i < 4; i++) {
            s[i][0] = 0.f;
            s[i][1] = 0.f;
        }
        for (int kk = 0; kk < DQK; kk += 4) {
            float4 k0v = *(float4*)&Ks[tk * QSTR + kk];
            float4 k1v = *(float4*)&Ks[(tk + 1) * QSTR + kk];
#pragma unroll
            for (int i = 0; i < 4; i++) {
                float4 qv = *(float4*)&Qs[(tq + i) * QSTR + kk];
                s[i][0] += qv.x * k0v.x + qv.y * k0v.y + qv.z * k0v.z + qv.w * k0v.w;
                s[i][1] += qv.x * k1v.x + qv.y * k1v.y + qv.z * k1v.z + qv.w * k1v.w;
            }
        }
#pragma unroll
        for (int i = 0; i < 4; i++)
#pragma unroll
            for (int j = 0; j < 2; j++) {
                int kg = k0 + tk + j, qg = q0 + tq + i;
                Ss[(tq + i) * SSTR + tk + j] = (kg <= qg) ? s[i][j] : -1e30f;
            }
        __syncthreads();

        if (tid < BQ) {
            const int r = tid;
            float mo = m_sh[r];
            float mx = mo;
#pragma unroll
            for (int k = 0; k < BKK; k++) mx = fmaxf(mx, Ss[r * SSTR + k]);
            float corr = __expf(mo - mx);
            float sum = 0.f;
#pragma unroll
            for (int k = 0; k < BKK; k++) {
                float p = __expf(Ss[r * SSTR + k] - mx);
                Ss[r * SSTR + k] = p;
                sum += p;
            }
            l_sh[r] = l_sh[r] * corr + sum;
            m_sh[r] = mx;
            c_sh[r] = corr;
        }
        __syncthreads();

        const float corr = c_sh[qrow];
#pragma unroll
        for (int i = 0; i < 32; i++) acc[i] *= corr;
        for (int k = 0; k < BKK; k++) {
            const float p = Ss[qrow * SSTR + k];
            const float* vr = &Vs[k * VSTR + dbase];
#pragma unroll
            for (int i = 0; i < 32; i += 4) {
                float4 vv = *(const float4*)&vr[i];
                acc[i] += p * vv.x;
                acc[i + 1] += p * vv.y;
                acc[i + 2] += p * vv.z;
                acc[i + 3] += p * vv.w;
            }
        }
    }
    __syncthreads();
    const float inv_l = 1.f / l_sh[qrow];
    float* orow = out + (size_t)(q0 + qrow) * (NH * DV) + h * DV + dbase;
#pragma unroll
    for (int i = 0; i < 32; i += 4) {
        float4 o = make_float4(acc[i] * inv_l, acc[i + 1] * inv_l,
                               acc[i + 2] * inv_l, acc[i + 3] * inv_l);
        *(float4*)&orow[i] = o;
    }
}

// ---------------- launch ---------------------------------------------------
static void run_split(const float* in, __nv_bfloat16* hi, __nv_bfloat16* lo,
                      int rows, int cols, int ostride) {
    dim3 grid((ostride + 255) / 256, rows);
    split_kernel<<<grid, 256>>>(in, hi, lo, cols, ostride);
}
static void run_gemm(const __nv_bfloat16* Ah, const __nv_bfloat16* Al,
                     const __nv_bfloat16* Bh, const __nv_bfloat16* Bl, float* C,
                     int M, int N, int K) {
    gemm_bf16x3<<<dim3(N / GBN, M / GBM), 256, GEMM_SMEM_BYTES>>>(Ah, Al, Bh, Bl,
                                                                  C, M, N, K);
}

extern "C" void kernel_launch(void* const* d_in, const int* in_sizes, int n_in,
                              void* d_out, int out_size) {
    const int* positions = (const int*)d_in[0];
    const float* hidden = (const float*)d_in[1];
    const float* w_qa = (const float*)d_in[2];
    const float* gamma_q = (const float*)d_in[3];
    const float* w_qb = (const float*)d_in[4];
    const float* w_kva = (const float*)d_in[5];
    const float* gamma_kv = (const float*)d_in[6];
    const float* w_kvb = (const float*)d_in[7];
    const float* w_o = (const float*)d_in[8];
    float* out = (float*)d_out;

    float *qc, *q, *kv, *kvc, *kvup, *qf, *kf, *v, *attn;
    cudaGetSymbolAddress((void**)&qc, g_qc);
    cudaGetSymbolAddress((void**)&q, g_q);
    cudaGetSymbolAddress((void**)&kv, g_kv);
    cudaGetSymbolAddress((void**)&kvc, g_kvc);
    cudaGetSymbolAddress((void**)&kvup, g_kvup);
    cudaGetSymbolAddress((void**)&qf, g_qfull);
    cudaGetSymbolAddress((void**)&kf, g_kfull);
    cudaGetSymbolAddress((void**)&v, g_vbuf);
    cudaGetSymbolAddress((void**)&attn, g_attn);

    __nv_bfloat16 *hid_h, *hid_l, *wqa_h, *wqa_l, *wqb_h, *wqb_l;
    __nv_bfloat16 *wkva_h, *wkva_l, *wkvb_h, *wkvb_l, *wo_h, *wo_l;
    __nv_bfloat16 *qc_h, *qc_l, *kvc_h, *kvc_l, *at_h, *at_l;
    cudaGetSymbolAddress((void**)&hid_h, g_hid_h);
    cudaGetSymbolAddress((void**)&hid_l, g_hid_l);
    cudaGetSymbolAddress((void**)&wqa_h, g_wqa_h);
    cudaGetSymbolAddress((void**)&wqa_l, g_wqa_l);
    cudaGetSymbolAddress((void**)&wqb_h, g_wqb_h);
    cudaGetSymbolAddress((void**)&wqb_l, g_wqb_l);
    cudaGetSymbolAddress((void**)&wkva_h, g_wkva_h);
    cudaGetSymbolAddress((void**)&wkva_l, g_wkva_l);
    cudaGetSymbolAddress((void**)&wkvb_h, g_wkvb_h);
    cudaGetSymbolAddress((void**)&wkvb_l, g_wkvb_l);
    cudaGetSymbolAddress((void**)&wo_h, g_wo_h);
    cudaGetSymbolAddress((void**)&wo_l, g_wo_l);
    cudaGetSymbolAddress((void**)&qc_h, g_qc_h);
    cudaGetSymbolAddress((void**)&qc_l, g_qc_l);
    cudaGetSymbolAddress((void**)&kvc_h, g_kvc_h);
    cudaGetSymbolAddress((void**)&kvc_l, g_kvc_l);
    cudaGetSymbolAddress((void**)&at_h, g_at_h);
    cudaGetSymbolAddress((void**)&at_l, g_at_l);

    cudaFuncSetAttribute(gemm_bf16x3, cudaFuncAttributeMaxDynamicSharedMemorySize,
                         GEMM_SMEM_BYTES);
    cudaFuncSetAttribute(attn_kernel, cudaFuncAttributeMaxDynamicSharedMemorySize,
                         ATTN_SMEM_BYTES);

    // ---- split inputs/weights to (hi, lo) bf16 ----
    run_split(hidden, hid_h, hid_l, TT, HIDDEN, HIDDEN);
    run_split(w_qa, wqa_h, wqa_l, HIDDEN, QLORA, QLORA);
    run_split(w_qb, wqb_h, wqb_l, QLORA, NH * DQK, NH * DQK);
    run_split(w_kva, wkva_h, wkva_l, HIDDEN, KVLORA + DR, NKVP);  // zero-padded
    run_split(w_kvb, wkvb_h, wkvb_l, KVLORA, NH * DKV, NH * DKV);
    run_split(w_o, wo_h, wo_l, NH * DV, HIDDEN, HIDDEN);

    // 1. q_c_raw = hidden @ w_qa     (2048 x 5120 x 1536)
    run_gemm(hid_h, hid_l, wqa_h, wqa_l, qc, TT, QLORA, HIDDEN);
    // 2. rmsnorm(q_c) in place, then split
    rmsnorm_kernel<<<TT, 256>>>(qc, gamma_q, qc, QLORA, QLORA, QLORA);
    run_split(qc, qc_h, qc_l, TT, QLORA, QLORA);
    // 3. q = q_c @ w_qb              (2048 x 1536 x 6144)
    run_gemm(qc_h, qc_l, wqb_h, wqb_l, q, TT, NH * DQK, QLORA);
    // 4. kv = hidden @ w_kva         (2048 x 5120 x 640-padded)
    run_gemm(hid_h, hid_l, wkva_h, wkva_l, kv, TT, NKVP, HIDDEN);
    // 5. kv_c = rmsnorm(kv[:, :512]), then split
    rmsnorm_kernel<<<TT, 256>>>(kv, gamma_kv, kvc, KVLORA, NKVP, KVLORA);
    run_split(kvc, kvc_h, kvc_l, TT, KVLORA, KVLORA);
    // 6. kv_up = kv_c @ w_kvb        (2048 x 512 x 8192)
    run_gemm(kvc_h, kvc_l, wkvb_h, wkvb_l, kvup, TT, NH * DKV, KVLORA);
    // 7. pack + RoPE
    pack_rope_kernel<<<dim3(TT, NH), DQK>>>(positions, q, kv, kvup, qf, kf, v);
    // 8. attention
    attn_kernel<<<dim3(TT / BQ, NH), 256, ATTN_SMEM_BYTES>>>(qf, kf, v, attn);
    // 9. out = attn @ w_o            (2048 x 4096 x 5120), split attn first
    run_split(attn, at_h, at_l, TT, NH * DV, NH * DV);
    run_gemm(at_h, at_l, wo_h, wo_l, out, TT, HIDDEN, NH * DV);
}

// round 7
// speedup vs baseline: 3.7573x; 2.4042x over previous
#include <cuda_runtime.h>
#include <cuda_bf16.h>
#include <math.h>
#include <stdint.h>

#define TT 2048
#define HIDDEN 5120
#define NH 32
#define DQ 128
#define DR 64
#define DV 128
#define QLORA 1536
#define KVLORA 512
#define DQK 192   // DQ + DR
#define DKV 256   // DQ + DV
#define NKVP 640  // kv GEMM N padded to 128 multiple

// ---------------- fp32 scratch ---------------------------------------------
__device__ float g_qc[TT * QLORA];
__device__ float g_q[TT * NH * DQK];
__device__ float g_kv[TT * NKVP];
__device__ float g_kvup[TT * NH * DKV];

// ---------------- bf16 split scratch ----------------------------------------
__device__ __nv_bfloat16 g_hid_h[(size_t)TT * HIDDEN], g_hid_l[(size_t)TT * HIDDEN];
__device__ __nv_bfloat16 g_wqa_h[(size_t)HIDDEN * QLORA], g_wqa_l[(size_t)HIDDEN * QLORA];
__device__ __nv_bfloat16 g_wqb_h[(size_t)QLORA * NH * DQK], g_wqb_l[(size_t)QLORA * NH * DQK];
__device__ __nv_bfloat16 g_wkva_h[(size_t)HIDDEN * NKVP], g_wkva_l[(size_t)HIDDEN * NKVP];
__device__ __nv_bfloat16 g_wkvb_h[(size_t)KVLORA * NH * DKV], g_wkvb_l[(size_t)KVLORA * NH * DKV];
__device__ __nv_bfloat16 g_wo_h[(size_t)NH * DV * HIDDEN], g_wo_l[(size_t)NH * DV * HIDDEN];
__device__ __nv_bfloat16 g_qc_h[(size_t)TT * QLORA], g_qc_l[(size_t)TT * QLORA];
__device__ __nv_bfloat16 g_kvc_h[(size_t)TT * KVLORA], g_kvc_l[(size_t)TT * KVLORA];
__device__ __nv_bfloat16 g_at_h[(size_t)TT * NH * DV], g_at_l[(size_t)TT * NH * DV];
__device__ __nv_bfloat16 g_qf_h[(size_t)NH * TT * DQK], g_qf_l[(size_t)NH * TT * DQK];
__device__ __nv_bfloat16 g_kf_h[(size_t)NH * TT * DQK], g_kf_l[(size_t)NH * TT * DQK];
__device__ __nv_bfloat16 g_v_h[(size_t)NH * TT * DV], g_v_l[(size_t)NH * TT * DV];

// ---------------- helpers ---------------------------------------------------
__device__ __forceinline__ void cp16(uint32_t dst, const void* src) {
    asm volatile("cp.async.cg.shared.global [%0], [%1], 16;\n" ::"r"(dst),
                 "l"(src));
}
__device__ __forceinline__ void ldsm4(uint32_t* r, uint32_t addr) {
    asm volatile("ldmatrix.sync.aligned.m8n8.x4.shared.b16 {%0,%1,%2,%3}, [%4];"
                 : "=r"(r[0]), "=r"(r[1]), "=r"(r[2]), "=r"(r[3])
                 : "r"(addr));
}
__device__ __forceinline__ void ldsm4t(uint32_t* r, uint32_t addr) {
    asm volatile(
        "ldmatrix.sync.aligned.m8n8.x4.trans.shared.b16 {%0,%1,%2,%3}, [%4];"
        : "=r"(r[0]), "=r"(r[1]), "=r"(r[2]), "=r"(r[3])
        : "r"(addr));
}
__device__ __forceinline__ void mma16816(float* d, const uint32_t* a,
                                         const uint32_t b0, const uint32_t b1) {
    asm volatile(
        "mma.sync.aligned.m16n8k16.row.col.f32.bf16.bf16.f32 "
        "{%0,%1,%2,%3},{%4,%5,%6,%7},{%8,%9},{%0,%1,%2,%3};"
        : "+f"(d[0]), "+f"(d[1]), "+f"(d[2]), "+f"(d[3])
        : "r"(a[0]), "r"(a[1]), "r"(a[2]), "r"(a[3]), "r"(b0), "r"(b1));
}
__device__ __forceinline__ void split2(float a, float b, uint32_t& h,
                                       uint32_t& l) {
    __nv_bfloat16 ha = __float2bfloat16(a), hb = __float2bfloat16(b);
    __nv_bfloat162 hh;
    hh.x = ha;
    hh.y = hb;
    h = *reinterpret_cast<uint32_t*>(&hh);
    __nv_bfloat162 ll;
    ll.x = __float2bfloat16(a - __bfloat162float(ha));
    ll.y = __float2bfloat16(b - __bfloat162float(hb));
    l = *reinterpret_cast<uint32_t*>(&ll);
}

// ---------------- split fp32 -> (hi, lo) bf16, optional zero-padded cols ----
__global__ void split_kernel(const float* __restrict__ in,
                             __nv_bfloat16* __restrict__ hi,
                             __nv_bfloat16* __restrict__ lo, int cols,
                             int ostride) {
    const int r = blockIdx.y;
    for (int c = blockIdx.x * blockDim.x + threadIdx.x; c < ostride;
         c += gridDim.x * blockDim.x) {
        float v = (c < cols) ? in[(size_t)r * cols + c] : 0.f;
        __nv_bfloat16 h = __float2bfloat16(v);
        size_t o = (size_t)r * ostride + c;
        hi[o] = h;
        lo[o] = __float2bfloat16(v - __bfloat162float(h));
    }
}

// ---------------- tensor-core GEMM (split bf16, 3 MMAs) ---------------------
#define GBM 128
#define GBN 128
#define GBK 32
#define ASTR 40
#define BSTR 136
#define A_STAGE (GBM * ASTR)
#define B_STAGE (GBK * BSTR)
#define GEMM_SMEM_BYTES ((2 * 2 * A_STAGE + 2 * 2 * B_STAGE) * 2)

__global__ __launch_bounds__(256, 1) void gemm_bf16x3(
    const __nv_bfloat16* __restrict__ Ah, const __nv_bfloat16* __restrict__ Al,
    const __nv_bfloat16* __restrict__ Bh, const __nv_bfloat16* __restrict__ Bl,
    float* __restrict__ C, int M, int N, int K) {
    extern __shared__ __nv_bfloat16 sm[];
    const int tid = threadIdx.x;
    const int lane = tid & 31, wid = tid >> 5;
    const int wm = (wid >> 1) * 32, wn = (wid & 1) * 64;
    const int bm0 = blockIdx.y * GBM, bn0 = blockIdx.x * GBN;

    const uint32_t base = (uint32_t)__cvta_generic_to_shared(sm);
    const uint32_t sAh_b = base;
    const uint32_t sAl_b = base + 2 * A_STAGE * 2;
    const uint32_t sBh_b = base + 4 * A_STAGE * 2;
    const uint32_t sBl_b = sBh_b + 2 * B_STAGE * 2;

    auto prefetch = [&](int k0, int st) {
#pragma unroll
        for (int i = 0; i < 2; i++) {
            int c = tid + i * 256;
            int r = c >> 2, ch = (c & 3) * 8;
            size_t goff = (size_t)(bm0 + r) * K + k0 + ch;
            uint32_t soff = (uint32_t)(st * A_STAGE + r * ASTR + ch) * 2;
            cp16(sAh_b + soff, Ah + goff);
            cp16(sAl_b + soff, Al + goff);
        }
#pragma unroll
        for (int i = 0; i < 2; i++) {
            int c = tid + i * 256;
            int r = c >> 4, ch = (c & 15) * 8;
            size_t goff = (size_t)(k0 + r) * N + bn0 + ch;
            uint32_t soff = (uint32_t)(st * B_STAGE + r * BSTR + ch) * 2;
            cp16(sBh_b + soff, Bh + goff);
            cp16(sBl_b + soff, Bl + goff);
        }
    };

    float acc[2][8][4];
#pragma unroll
    for (int mi = 0; mi < 2; mi++)
#pragma unroll
        for (int ni = 0; ni < 8; ni++)
#pragma unroll
            for (int j = 0; j < 4; j++) acc[mi][ni][j] = 0.f;

    const int KT = K / GBK;
    prefetch(0, 0);
    asm volatile("cp.async.commit_group;\n");

    for (int kt = 0; kt < KT; kt++) {
        const int st = kt & 1;
        if (kt + 1 < KT) prefetch((kt + 1) * GBK, st ^ 1);
        asm volatile("cp.async.commit_group;\n");
        asm volatile("cp.async.wait_group 1;\n");
        __syncthreads();

#pragma unroll
        for (int kk = 0; kk < GBK; kk += 16) {
            uint32_t ah[2][4], al[2][4];
#pragma unroll
            for (int mi = 0; mi < 2; mi++) {
                int r = wm + mi * 16 + (lane & 15);
                int cc = kk + ((lane >> 4) << 3);
                uint32_t off = (uint32_t)(st * A_STAGE + r * ASTR + cc) * 2;
                ldsm4(ah[mi], sAh_b + off);
                ldsm4(al[mi], sAl_b + off);
            }
            uint32_t bh[4][4], bl[4][4];
#pragma unroll
            for (int n2 = 0; n2 < 4; n2++) {
                int kr = kk + (lane & 15);
                int nc = wn + n2 * 16 + ((lane >> 4) << 3);
                uint32_t off = (uint32_t)(st * B_STAGE + kr * BSTR + nc) * 2;
                ldsm4t(bh[n2], sBh_b + off);
                ldsm4t(bl[n2], sBl_b + off);
            }
#pragma unroll
            for (int mi = 0; mi < 2; mi++)
#pragma unroll
                for (int ni = 0; ni < 8; ni++) {
                    const int n2 = ni >> 1, sl = (ni & 1) * 2;
                    mma16816(acc[mi][ni], ah[mi], bh[n2][sl], bh[n2][sl + 1]);
                    mma16816(acc[mi][ni], ah[mi], bl[n2][sl], bl[n2][sl + 1]);
                    mma16816(acc[mi][ni], al[mi], bh[n2][sl], bh[n2][sl + 1]);
                }
        }
        __syncthreads();
    }

#pragma unroll
    for (int mi = 0; mi < 2; mi++)
#pragma unroll
        for (int ni = 0; ni < 8; ni++) {
            int row = bm0 + wm + mi * 16 + (lane >> 2);
            int col = bn0 + wn + ni * 8 + (lane & 3) * 2;
            *(float2*)&C[(size_t)row * N + col] =
                make_float2(acc[mi][ni][0], acc[mi][ni][1]);
            *(float2*)&C[(size_t)(row + 8) * N + col] =
                make_float2(acc[mi][ni][2], acc[mi][ni][3]);
        }
}

// ---------------- RMSNorm fused with bf16 split ----------------------------
__global__ void rmsnorm_split_kernel(const float* __restrict__ in,
                                     const float* __restrict__ gamma,
                                     __nv_bfloat16* __restrict__ hi,
                                     __nv_bfloat16* __restrict__ lo, int D,
                                     int in_stride) {
    const int row = blockIdx.x;
    const float* x = in + (size_t)row * in_stride;
    float s = 0.f;
    for (int d = threadIdx.x; d < D; d += blockDim.x) {
        float v = x[d];
        s += v * v;
    }
    __shared__ float red[32];
#pragma unroll
    for (int o = 16; o; o >>= 1) s += __shfl_xor_sync(0xffffffffu, s, o);
    if ((threadIdx.x & 31) == 0) red[threadIdx.x >> 5] = s;
    __syncthreads();
    if (threadIdx.x < 32) {
        float v = (threadIdx.x < (blockDim.x >> 5)) ? red[threadIdx.x] : 0.f;
#pragma unroll
        for (int o = 16; o; o >>= 1) v += __shfl_xor_sync(0xffffffffu, v, o);
        if (threadIdx.x == 0) red[0] = v;
    }
    __syncthreads();
    const float r = rsqrtf(red[0] / (float)D + 1e-6f);
    for (int d = threadIdx.x; d < D; d += blockDim.x) {
        float v = x[d] * r * gamma[d];
        __nv_bfloat16 h = __float2bfloat16(v);
        hi[(size_t)row * D + d] = h;
        lo[(size_t)row * D + d] = __float2bfloat16(v - __bfloat162float(h));
    }
}

// ---------------- pack + RoPE -> bf16 hi/lo --------------------------------
__global__ void pack_rope_kernel(const int* __restrict__ pos,
                                 const float* __restrict__ q,
                                 const float* __restrict__ kv,
                                 const float* __restrict__ kvup,
                                 __nv_bfloat16* __restrict__ qf_h,
                                 __nv_bfloat16* __restrict__ qf_l,
                                 __nv_bfloat16* __restrict__ kf_h,
                                 __nv_bfloat16* __restrict__ kf_l,
                                 __nv_bfloat16* __restrict__ v_h,
                                 __nv_bfloat16* __restrict__ v_l) {
    const int t = blockIdx.x;
    const int h = blockIdx.y;
    const int d = threadIdx.x;  // 0..191
    const float scale = rsqrtf((float)DQK);
    float qf, kf;
    if (d < DQ) {
        qf = q[(size_t)t * (NH * DQK) + h * DQK + d];
        kf = kvup[(size_t)t * (NH * DKV) + h * DKV + d];
        float vv = kvup[(size_t)t * (NH * DKV) + h * DKV + DQ + d];
        __nv_bfloat16 vh = __float2bfloat16(vv);
        size_t vo = ((size_t)h * TT + t) * DV + d;
        v_h[vo] = vh;
        v_l[vo] = __float2bfloat16(vv - __bfloat162float(vh));
    } else {
        const int d2 = d - DQ;  // 0..63
        const float p = (float)pos[t];
        const float ang = p * powf(10000.f, -((float)(d2 & 31)) / 32.f);
        float c, s;
        sincosf(ang, &s, &c);
        const size_t qb = (size_t)t * (NH * DQK) + h * DQK + DQ;
        float xq = q[qb + d2];
        float xq_o = (d2 & 1) ? q[qb + d2 - 1] : -q[qb + d2 + 1];
        qf = xq * c + xq_o * s;
        const size_t kb = (size_t)t * NKVP + KVLORA;
        float xk = kv[kb + d2];
        float xk_o = (d2 & 1) ? kv[kb + d2 - 1] : -kv[kb + d2 + 1];
        kf = xk * c + xk_o * s;
    }
    qf *= scale;
    size_t o = ((size_t)h * TT + t) * DQK + d;
    __nv_bfloat16 qh = __float2bfloat16(qf);
    qf_h[o] = qh;
    qf_l[o] = __float2bfloat16(qf - __bfloat162float(qh));
    __nv_bfloat16 kh = __float2bfloat16(kf);
    kf_h[o] = kh;
    kf_l[o] = __float2bfloat16(kf - __bfloat162float(kh));
}

// ---------------- tensor-core flash attention (causal) ----------------------
#define ABQ 128
#define ABK 32
#define AQS 200  // q/k smem row stride in bf16 elems
#define AVS 136  // v smem row stride
#define OFF_QH 0
#define OFF_QL (ABQ * AQS * 2)
#define OFF_KH (2 * ABQ * AQS * 2)
#define KSTAGE (ABK * AQS * 2)
#define OFF_KL (OFF_KH + 2 * KSTAGE)
#define OFF_VH (OFF_KL + 2 * KSTAGE)
#define VSTAGE (ABK * AVS * 2)
#define OFF_VL (OFF_VH + 2 * VSTAGE)
#define ATTN2_SMEM (OFF_VL + 2 * VSTAGE)  // 188416 bytes

__global__ __launch_bounds__(256, 1) void attn_mma_kernel(
    const __nv_bfloat16* __restrict__ qh_g, const __nv_bfloat16* __restrict__ ql_g,
    const __nv_bfloat16* __restrict__ kh_g, const __nv_bfloat16* __restrict__ kl_g,
    const __nv_bfloat16* __restrict__ vh_g, const __nv_bfloat16* __restrict__ vl_g,
    __nv_bfloat16* __restrict__ oh_g, __nv_bfloat16* __restrict__ ol_g) {
    extern __shared__ char smc[];
    const uint32_t base = (uint32_t)__cvta_generic_to_shared(smc);
    const int tid = threadIdx.x, lane = tid & 31, wid = tid >> 5;
    const int warpM = wid * 16;
    const int q0 = blockIdx.x * ABQ;
    const int h = blockIdx.y;
    const __nv_bfloat16* qhp = qh_g + (size_t)h * TT * DQK;
    const __nv_bfloat16* qlp = ql_g + (size_t)h * TT * DQK;
    const __nv_bfloat16* khp = kh_g + (size_t)h * TT * DQK;
    const __nv_bfloat16* klp = kl_g + (size_t)h * TT * DQK;
    const __nv_bfloat16* vhp = vh_g + (size_t)h * TT * DV;
    const __nv_bfloat16* vlp = vl_g + (size_t)h * TT * DV;

    // load Q (hi+lo) once
#pragma unroll
    for (int i = 0; i < 12; i++) {
        int c = tid + i * 256;
        int r = c / 24, ch = c - r * 24;
        size_t g = (size_t)(q0 + r) * DQK + ch * 8;
        uint32_t so = (uint32_t)(r * AQS + ch * 8) * 2;
        cp16(base + OFF_QH + so, qhp + g);
        cp16(base + OFF_QL + so, qlp + g);
    }
    auto ldKV = [&](int k0, int st) {
#pragma unroll
        for (int i = 0; i < 3; i++) {
            int c = tid + i * 256;
            int r = c / 24, ch = c - r * 24;
            size_t g = (size_t)(k0 + r) * DQK + ch * 8;
            uint32_t so = (uint32_t)(st * KSTAGE) + (uint32_t)(r * AQS + ch * 8) * 2;
            cp16(base + OFF_KH + so, khp + g);
            cp16(base + OFF_KL + so, klp + g);
        }
#pragma unroll
        for (int i = 0; i < 2; i++) {
            int c = tid + i * 256;
            int r = c >> 4, ch = c & 15;
            size_t g = (size_t)(k0 + r) * DV + ch * 8;
            uint32_t so = (uint32_t)(st * VSTAGE) + (uint32_t)(r * AVS + ch * 8) * 2;
            cp16(base + OFF_VH + so, vhp + g);
            cp16(base + OFF_VL + so, vlp + g);
        }
    };
    ldKV(0, 0);
    asm volatile("cp.async.commit_group;\n");

    float m0 = -1e30f, m1 = -1e30f, l0 = 0.f, l1 = 0.f;
    float acc[16][4];
#pragma unroll
    for (int i = 0; i < 16; i++)
#pragma unroll
        for (int j = 0; j < 4; j++) acc[i][j] = 0.f;

    const int nkb = (q0 + ABQ) / ABK;
    const int r0g = q0 + warpM + (lane >> 2);

    for (int kb = 0; kb < nkb; kb++) {
        const int st = kb & 1;
        if (kb + 1 < nkb) ldKV((kb + 1) * ABK, st ^ 1);
        asm volatile("cp.async.commit_group;\n");
        asm volatile("cp.async.wait_group 1;\n");
        __syncthreads();

        // ---- S = Q K^T (3-way split) ----
        float s[4][4];
#pragma unroll
        for (int t = 0; t < 4; t++)
#pragma unroll
            for (int j = 0; j < 4; j++) s[t][j] = 0.f;

        const uint32_t kbB = base + (uint32_t)(st * KSTAGE);
#pragma unroll
        for (int ks = 0; ks < 12; ks++) {
            uint32_t qa_h[4], qa_l[4];
            uint32_t offq =
                (uint32_t)(((warpM + (lane & 15)) * AQS + ks * 16 +
                            ((lane >> 4) << 3)) * 2);
            ldsm4(qa_h, base + OFF_QH + offq);
            ldsm4(qa_l, base + OFF_QL + offq);
            uint32_t kh0[4], kh1[4], kl0[4], kl1[4];
            uint32_t offk =
                (uint32_t)((((lane & 7) + ((lane >> 4) << 3)) * AQS + ks * 16 +
                            (((lane >> 3) & 1) << 3)) * 2);
            ldsm4(kh0, kbB + OFF_KH + offk);
            ldsm4(kh1, kbB + OFF_KH + offk + 16 * AQS * 2);
            ldsm4(kl0, kbB + OFF_KL + offk);
            ldsm4(kl1, kbB + OFF_KL + offk + 16 * AQS * 2);
            mma16816(s[0], qa_h, kh0[0], kh0[1]);
            mma16816(s[0], qa_h, kl0[0], kl0[1]);
            mma16816(s[0], qa_l, kh0[0], kh0[1]);
            mma16816(s[1], qa_h, kh0[2], kh0[3]);
            mma16816(s[1], qa_h, kl0[2], kl0[3]);
            mma16816(s[1], qa_l, kh0[2], kh0[3]);
            mma16816(s[2], qa_h, kh1[0], kh1[1]);
            mma16816(s[2], qa_h, kl1[0], kl1[1]);
            mma16816(s[2], qa_l, kh1[0], kh1[1]);
            mma16816(s[3], qa_h, kh1[2], kh1[3]);
            mma16816(s[3], qa_h, kl1[2], kl1[3]);
            mma16816(s[3], qa_l, kh1[2], kh1[3]);
        }

        // ---- causal mask ----
        const int k0g = kb * ABK;
        if (k0g + ABK - 1 > q0 + warpM) {
#pragma unroll
            for (int t = 0; t < 4; t++) {
                int cb = k0g + t * 8 + ((lane & 3) << 1);
                if (cb > r0g) s[t][0] = -1e30f;
                if (cb + 1 > r0g) s[t][1] = -1e30f;
                if (cb > r0g + 8) s[t][2] = -1e30f;
                if (cb + 1 > r0g + 8) s[t][3] = -1e30f;
            }
        }

        // ---- online softmax ----
        float mx0 = -1e30f, mx1 = -1e30f;
#pragma unroll
        for (int t = 0; t < 4; t++) {
            mx0 = fmaxf(mx0, fmaxf(s[t][0], s[t][1]));
            mx1 = fmaxf(mx1, fmaxf(s[t][2], s[t][3]));
        }
        mx0 = fmaxf(mx0, __shfl_xor_sync(0xffffffffu, mx0, 1));
        mx0 = fmaxf(mx0, __shfl_xor_sync(0xffffffffu, mx0, 2));
        mx1 = fmaxf(mx1, __shfl_xor_sync(0xffffffffu, mx1, 1));
        mx1 = fmaxf(mx1, __shfl_xor_sync(0xffffffffu, mx1, 2));
        float mn0 = fmaxf(m0, mx0), mn1 = fmaxf(m1, mx1);
        float c0 = __expf(m0 - mn0), c1 = __expf(m1 - mn1);
        m0 = mn0;
        m1 = mn1;
        float sum0 = 0.f, sum1 = 0.f;
#pragma unroll
        for (int t = 0; t < 4; t++) {
            s[t][0] = __expf(s[t][0] - mn0);
            s[t][1] = __expf(s[t][1] - mn0);
            s[t][2] = __expf(s[t][2] - mn1);
            s[t][3] = __expf(s[t][3] - mn1);
            sum0 += s[t][0] + s[t][1];
            sum1 += s[t][2] + s[t][3];
        }
        sum0 += __shfl_xor_sync(0xffffffffu, sum0, 1);
        sum0 += __shfl_xor_sync(0xffffffffu, sum0, 2);
        sum1 += __shfl_xor_sync(0xffffffffu, sum1, 1);
        sum1 += __shfl_xor_sync(0xffffffffu, sum1, 2);
        l0 = l0 * c0 + sum0;
        l1 = l1 * c1 + sum1;
#pragma unroll
        for (int vt = 0; vt < 16; vt++) {
            acc[vt][0] *= c0;
            acc[vt][1] *= c0;
            acc[vt][2] *= c1;
            acc[vt][3] *= c1;
        }

        // ---- O += P V (3-way split; P packed from S accumulators) ----
        const uint32_t vbB = base + (uint32_t)(st * VSTAGE);
#pragma unroll
        for (int ks2 = 0; ks2 < 2; ks2++) {
            uint32_t pa_h[4], pa_l[4];
            split2(s[2 * ks2][0], s[2 * ks2][1], pa_h[0], pa_l[0]);
            split2(s[2 * ks2][2], s[2 * ks2][3], pa_h[1], pa_l[1]);
            split2(s[2 * ks2 + 1][0], s[2 * ks2 + 1][1], pa_h[2], pa_l[2]);
            split2(s[2 * ks2 + 1][2], s[2 * ks2 + 1][3], pa_h[3], pa_l[3]);
#pragma unroll
            for (int vt2 = 0; vt2 < 8; vt2++) {
                uint32_t offv =
                    (uint32_t)(((ks2 * 16 + (lane & 15)) * AVS + vt2 * 16 +
                                ((lane >> 4) << 3)) * 2);
                uint32_t vb_h[4], vb_l[4];
                ldsm4t(vb_h, vbB + OFF_VH + offv);
                ldsm4t(vb_l, vbB + OFF_VL + offv);
                mma16816(acc[2 * vt2], pa_h, vb_h[0], vb_h[1]);
                mma16816(acc[2 * vt2], pa_h, vb_l[0], vb_l[1]);
                mma16816(acc[2 * vt2], pa_l, vb_h[0], vb_h[1]);
                mma16816(acc[2 * vt2 + 1], pa_h, vb_h[2], vb_h[3]);
                mma16816(acc[2 * vt2 + 1], pa_h, vb_l[2], vb_l[3]);
                mma16816(acc[2 * vt2 + 1], pa_l, vb_h[2], vb_h[3]);
            }
        }
        __syncthreads();
    }

    // ---- epilogue: write attn as split bf16 [t][NH*DV] ----
    const float il0 = 1.f / l0, il1 = 1.f / l1;
    const int t0 = q0 + warpM + (lane >> 2);
#pragma unroll
    for (int vt = 0; vt < 16; vt++) {
        int col = h * DV + vt * 8 + ((lane & 3) << 1);
        uint32_t h0, lo0, h1, lo1;
        split2(acc[vt][0] * il0, acc[vt][1] * il0, h0, lo0);
        split2(acc[vt][2] * il1, acc[vt][3] * il1, h1, lo1);
        size_t o0 = (size_t)t0 * (NH * DV) + col;
        size_t o1 = (size_t)(t0 + 8) * (NH * DV) + col;
        *reinterpret_cast<uint32_t*>(oh_g + o0) = h0;
        *reinterpret_cast<uint32_t*>(ol_g + o0) = lo0;
        *reinterpret_cast<uint32_t*>(oh_g + o1) = h1;
        *reinterpret_cast<uint32_t*>(ol_g + o1) = lo1;
    }
}

// ---------------- launch ---------------------------------------------------
static void run_split(const float* in, __nv_bfloat16* hi, __nv_bfloat16* lo,
                      int rows, int cols, int ostride) {
    dim3 grid((ostride + 255) / 256, rows);
    split_kernel<<<grid, 256>>>(in, hi, lo, cols, ostride);
}
static void run_gemm(const __nv_bfloat16* Ah, const __nv_bfloat16* Al,
                     const __nv_bfloat16* Bh, const __nv_bfloat16* Bl, float* C,
                     int M, int N, int K) {
    gemm_bf16x3<<<dim3(N / GBN, M / GBM), 256, GEMM_SMEM_BYTES>>>(Ah, Al, Bh, Bl,
                                                                  C, M, N, K);
}

extern "C" void kernel_launch(void* const* d_in, const int* in_sizes, int n_in,
                              void* d_out, int out_size) {
    const int* positions = (const int*)d_in[0];
    const float* hidden = (const float*)d_in[1];
    const float* w_qa = (const float*)d_in[2];
    const float* gamma_q = (const float*)d_in[3];
    const float* w_qb = (const float*)d_in[4];
    const float* w_kva = (const float*)d_in[5];
    const float* gamma_kv = (const float*)d_in[6];
    const float* w_kvb = (const float*)d_in[7];
    const float* w_o = (const float*)d_in[8];
    float* out = (float*)d_out;

    float *qc, *q, *kv, *kvup;
    cudaGetSymbolAddress((void**)&qc, g_qc);
    cudaGetSymbolAddress((void**)&q, g_q);
    cudaGetSymbolAddress((void**)&kv, g_kv);
    cudaGetSymbolAddress((void**)&kvup, g_kvup);

    __nv_bfloat16 *hid_h, *hid_l, *wqa_h, *wqa_l, *wqb_h, *wqb_l;
    __nv_bfloat16 *wkva_h, *wkva_l, *wkvb_h, *wkvb_l, *wo_h, *wo_l;
    __nv_bfloat16 *qc_h, *qc_l, *kvc_h, *kvc_l, *at_h, *at_l;
    __nv_bfloat16 *qf_h, *qf_l, *kf_h, *kf_l, *v_h, *v_l;
    cudaGetSymbolAddress((void**)&hid_h, g_hid_h);
    cudaGetSymbolAddress((void**)&hid_l, g_hid_l);
    cudaGetSymbolAddress((void**)&wqa_h, g_wqa_h);
    cudaGetSymbolAddress((void**)&wqa_l, g_wqa_l);
    cudaGetSymbolAddress((void**)&wqb_h, g_wqb_h);
    cudaGetSymbolAddress((void**)&wqb_l, g_wqb_l);
    cudaGetSymbolAddress((void**)&wkva_h, g_wkva_h);
    cudaGetSymbolAddress((void**)&wkva_l, g_wkva_l);
    cudaGetSymbolAddress((void**)&wkvb_h, g_wkvb_h);
    cudaGetSymbolAddress((void**)&wkvb_l, g_wkvb_l);
    cudaGetSymbolAddress((void**)&wo_h, g_wo_h);
    cudaGetSymbolAddress((void**)&wo_l, g_wo_l);
    cudaGetSymbolAddress((void**)&qc_h, g_qc_h);
    cudaGetSymbolAddress((void**)&qc_l, g_qc_l);
    cudaGetSymbolAddress((void**)&kvc_h, g_kvc_h);
    cudaGetSymbolAddress((void**)&kvc_l, g_kvc_l);
    cudaGetSymbolAddress((void**)&at_h, g_at_h);
    cudaGetSymbolAddress((void**)&at_l, g_at_l);
    cudaGetSymbolAddress((void**)&qf_h, g_qf_h);
    cudaGetSymbolAddress((void**)&qf_l, g_qf_l);
    cudaGetSymbolAddress((void**)&kf_h, g_kf_h);
    cudaGetSymbolAddress((void**)&kf_l, g_kf_l);
    cudaGetSymbolAddress((void**)&v_h, g_v_h);
    cudaGetSymbolAddress((void**)&v_l, g_v_l);

    cudaFuncSetAttribute(gemm_bf16x3, cudaFuncAttributeMaxDynamicSharedMemorySize,
                         GEMM_SMEM_BYTES);
    cudaFuncSetAttribute(attn_mma_kernel,
                         cudaFuncAttributeMaxDynamicSharedMemorySize, ATTN2_SMEM);

    // ---- split inputs/weights to (hi, lo) bf16 ----
    run_split(hidden, hid_h, hid_l, TT, HIDDEN, HIDDEN);
    run_split(w_qa, wqa_h, wqa_l, HIDDEN, QLORA, QLORA);
    run_split(w_qb, wqb_h, wqb_l, QLORA, NH * DQK, NH * DQK);
    run_split(w_kva, wkva_h, wkva_l, HIDDEN, KVLORA + DR, NKVP);  // zero-padded
    run_split(w_kvb, wkvb_h, wkvb_l, KVLORA, NH * DKV, NH * DKV);
    run_split(w_o, wo_h, wo_l, NH * DV, HIDDEN, HIDDEN);

    // 1. q_c_raw = hidden @ w_qa     (2048 x 5120 x 1536)
    run_gemm(hid_h, hid_l, wqa_h, wqa_l, qc, TT, QLORA, HIDDEN);
    // 2. rmsnorm(q_c) fused with split
    rmsnorm_split_kernel<<<TT, 256>>>(qc, gamma_q, qc_h, qc_l, QLORA, QLORA);
    // 3. q = q_c @ w_qb              (2048 x 1536 x 6144)
    run_gemm(qc_h, qc_l, wqb_h, wqb_l, q, TT, NH * DQK, QLORA);
    // 4. kv = hidden @ w_kva         (2048 x 5120 x 640-padded)
    run_gemm(hid_h, hid_l, wkva_h, wkva_l, kv, TT, NKVP, HIDDEN);
    // 5. kv_c = rmsnorm(kv[:, :512]) fused with split
    rmsnorm_split_kernel<<<TT, 256>>>(kv, gamma_kv, kvc_h, kvc_l, KVLORA, NKVP);
    // 6. kv_up = kv_c @ w_kvb        (2048 x 512 x 8192)
    run_gemm(kvc_h, kvc_l, wkvb_h, wkvb_l, kvup, TT, NH * DKV, KVLORA);
    // 7. pack + RoPE -> bf16 hi/lo
    pack_rope_kernel<<<dim3(TT, NH), DQK>>>(positions, q, kv, kvup, qf_h, qf_l,
                                            kf_h, kf_l, v_h, v_l);
    // 8. tensor-core flash attention -> split bf16 attn
    attn_mma_kernel<<<dim3(TT / ABQ, NH), 256, ATTN2_SMEM>>>(
        qf_h, qf_l, kf_h, kf_l, v_h, v_l, at_h, at_l);
    // 9. out = attn @ w_o            (2048 x 4096 x 5120)
    run_gemm(at_h, at_l, wo_h, wo_l, out, TT, HIDDEN, NH * DV);
}